// round 5
// baseline (speedup 1.0000x reference)
#include <cuda_runtime.h>
#include <cstdint>
#include <cstddef>

// out[b,j] = in2[b,j] * sum_i in1[b,i] * (sum_k w[i,j,k])
// B=16384, I=64, J=2048, K=64.

#define B_DIM 16384
#define I_DIM 64
#define J_DIM 2048
#define K_DIM 64

#define BM 128
#define BN 128
#define AS_STRIDE 132  // floats; 16B-aligned rows, 4-way-bounded STS conflicts

// Dynamic smem: As (64*132 floats) + Bs (64*128 floats) = 66560 B.
#define SMEM_BYTES ((I_DIM * AS_STRIDE + I_DIM * BN) * (int)sizeof(float))

// 512 KB scratch for the K-reduced weights, [i][j] row-major.
__device__ float g_w2[I_DIM * J_DIM];

// ---------------------------------------------------------------------------
// Kernel 1: w2[i,j] = sum_k w[i,j,k].
// 16 lanes per (i,j): one float4 per lane covers the 64 contiguous K floats
// (256B fully-coalesced per group, 512B per warp), then 4 xor-shuffles.
// ---------------------------------------------------------------------------
__global__ void reduce_w_kernel(const float* __restrict__ w) {
    const int tid = blockIdx.x * blockDim.x + threadIdx.x;
    const int grp = tid >> 4;        // (i,j) index, 0..131071
    const int sl  = tid & 15;        // sublane within 16-lane group
    const float4 v = reinterpret_cast<const float4*>(w)[(size_t)grp * 16 + sl];
    float s = (v.x + v.y) + (v.z + v.w);
    s += __shfl_xor_sync(0xffffffffu, s, 8);
    s += __shfl_xor_sync(0xffffffffu, s, 4);
    s += __shfl_xor_sync(0xffffffffu, s, 2);
    s += __shfl_xor_sync(0xffffffffu, s, 1);
    if (sl == 0) g_w2[grp] = s;
}

// ---------------------------------------------------------------------------
// Kernel 2: 128x128 tile GEMM (K depth = I = 64, single shot), 512 threads,
// per-thread 8(b) x 4(j). Accumulators are f32x2 pairs along b, so the A
// operand pair loads directly from smem (no duplication mov); only the 4
// B scalars need a mov.b64 {b,b} per i-iteration. Fused *in2 epilogue.
// 2 CTAs/SM -> 32 warps/SM (8 per SMSP) for latency hiding.
// ---------------------------------------------------------------------------
__global__ __launch_bounds__(512, 2)
void bilinear_kernel(const float* __restrict__ in1,
                     const float* __restrict__ in2,
                     float* __restrict__ out) {
    extern __shared__ float smem[];
    float* As = smem;                          // [i][b]  64 x 132 (b minor)
    float* Bs = smem + I_DIM * AS_STRIDE;      // [i][j]  64 x 128 (j minor)

    const int t  = threadIdx.x;
    const int tx = t & 31;   // j-group 0..31 (4 j each)
    const int ty = t >> 5;   // b-group 0..15 (8 b each)
    const int jBase = blockIdx.x * BN;
    const int bBase = blockIdx.y * BM;

    // --- load A transposed: in1 is [b][i] (i contiguous) -> As[i][b] ---
    #pragma unroll
    for (int r = 0; r < (BM * I_DIM) / 512; r++) {
        int gidx = t + r * 512;       // 0..8191
        int b = gidx >> 6;
        int i = gidx & 63;
        As[i * AS_STRIDE + b] = in1[(size_t)(bBase + b) * I_DIM + i];
    }

    // --- load Bs: g_w2[i][jBase..jBase+127], float4, fully coalesced ---
    #pragma unroll
    for (int r = 0; r < (I_DIM * BN / 4) / 512; r++) {
        int idx4 = t + r * 512;       // 0..2047
        int i  = idx4 >> 5;
        int jc = idx4 & 31;
        reinterpret_cast<float4*>(Bs)[i * (BN / 4) + jc] =
            reinterpret_cast<const float4*>(g_w2 + (size_t)i * J_DIM + jBase)[jc];
    }
    __syncthreads();

    // acc[mp][n]: f32x2 over b-pair (2mp, 2mp+1), j column tx*4+n.
    unsigned long long acc[4][4];
    #pragma unroll
    for (int mp = 0; mp < 4; mp++)
        #pragma unroll
        for (int n = 0; n < 4; n++)
            acc[mp][n] = 0ull;

    #pragma unroll 4
    for (int i = 0; i < I_DIM; i++) {
        // a: 8 consecutive b values -> 4 natural f32x2 pairs (broadcast across
        // the 32 lanes sharing ty: ~free on the smem crossbar).
        const ulonglong2 aA = *reinterpret_cast<const ulonglong2*>(&As[i * AS_STRIDE + ty * 8]);
        const ulonglong2 aB = *reinterpret_cast<const ulonglong2*>(&As[i * AS_STRIDE + ty * 8 + 4]);
        const float4 bv = *reinterpret_cast<const float4*>(&Bs[i * BN + tx * 4]);

        const unsigned long long ap[4] = {aA.x, aA.y, aB.x, aB.y};
        const float bs[4] = {bv.x, bv.y, bv.z, bv.w};

        #pragma unroll
        for (int n = 0; n < 4; n++) {
            unsigned long long bdup;
            asm("mov.b64 %0, {%1, %1};" : "=l"(bdup) : "f"(bs[n]));
            #pragma unroll
            for (int mp = 0; mp < 4; mp++) {
                asm("fma.rn.f32x2 %0, %1, %2, %0;"
                    : "+l"(acc[mp][n]) : "l"(ap[mp]), "l"(bdup));
            }
        }
    }

    // --- epilogue: out = acc * in2. Rows b = bBase + ty*8 + 2mp + {0,1}. ---
    #pragma unroll
    for (int mp = 0; mp < 4; mp++) {
        float lo[4], hi[4];
        #pragma unroll
        for (int n = 0; n < 4; n++) {
            asm("mov.b64 {%0, %1}, %2;" : "=f"(lo[n]), "=f"(hi[n]) : "l"(acc[mp][n]));
        }
        const size_t row0 = (size_t)(bBase + ty * 8 + 2 * mp) * J_DIM + jBase + tx * 4;
        const size_t row1 = row0 + J_DIM;

        const float4 c0 = *reinterpret_cast<const float4*>(&in2[row0]);
        float4 o0 = {lo[0] * c0.x, lo[1] * c0.y, lo[2] * c0.z, lo[3] * c0.w};
        *reinterpret_cast<float4*>(&out[row0]) = o0;

        const float4 c1 = *reinterpret_cast<const float4*>(&in2[row1]);
        float4 o1 = {hi[0] * c1.x, hi[1] * c1.y, hi[2] * c1.z, hi[3] * c1.w};
        *reinterpret_cast<float4*>(&out[row1]) = o1;
    }
}

// ---------------------------------------------------------------------------
extern "C" void kernel_launch(void* const* d_in, const int* in_sizes, int n_in,
                              void* d_out, int out_size) {
    (void)in_sizes; (void)n_in; (void)out_size;
    const float* in1 = (const float*)d_in[0];   // (16384, 64)
    const float* in2 = (const float*)d_in[1];   // (16384, 2048)
    const float* w   = (const float*)d_in[2];   // (64, 2048, 64)
    float* out = (float*)d_out;                 // (16384, 2048) fp32

    cudaFuncSetAttribute(bilinear_kernel,
                         cudaFuncAttributeMaxDynamicSharedMemorySize, SMEM_BYTES);

    // Kernel 1: 131072 (i,j) groups * 16 lanes / 256 = 8192 blocks.
    reduce_w_kernel<<<(I_DIM * J_DIM * 16) / 256, 256>>>(w);

    // Kernel 2: 16 x 128 blocks of 512 threads.
    dim3 grid(J_DIM / BN, B_DIM / BM);
    bilinear_kernel<<<grid, 512, SMEM_BYTES>>>(in1, in2, out);
}